// round 15
// baseline (speedup 1.0000x reference)
#include <cuda_runtime.h>
#include <cuda_fp16.h>
#include <cstdint>

#define BATCH 2
#define SEQ   2048
#define DIM   1024
#define NST   16
#define DTR   64
#define XD    96   /* dt_rank + 2*N */

#define MROWS (BATCH*SEQ) /* 4096 */

#define NC 8      /* scan chunks */
#define LC 256    /* chunk length = SEQ/NC */

#define SK 16     /* x_proj split-K factor */

// ---------------- scratch (allocation-free: __device__ globals) ----------------
__device__ float  g_xcin[(size_t)MROWS * DIM];    // 16.8 MB (in_proj xc-half, pre-conv)
__device__ __half g_gate[(size_t)MROWS * DIM];    // 8.4 MB  (silu(z), fp16)
__device__ float  g_xc[(size_t)MROWS * DIM];      // 16.8 MB (conv out, fp32 for x_proj)
__device__ __half g_xch[(size_t)MROWS * DIM];     // 8.4 MB  (conv out, fp16 for scan)
__device__ float  g_xdbl[(size_t)MROWS * XD];     // 1.6 MB
__device__ __half g_deltah[(size_t)MROWS * DIM];  // 8.4 MB  (fp16 delta)
// fp16 GEMM operands
__device__ __half g_xh[(size_t)MROWS * DIM];      // 8.4 MB
__device__ __half g_wh_in[(size_t)2 * DIM * DIM]; // 4.2 MB
__device__ __half g_wh_out[(size_t)DIM * DIM];    // 2.1 MB
__device__ __half g_wh_dt[(size_t)DIM * DTR];     // 0.13 MB
__device__ __half g_dtin[(size_t)MROWS * DTR];    // 0.5 MB
__device__ __half g_ygh[(size_t)MROWS * DIM];     // 8.4 MB
// x_proj split-K partials
__device__ float g_xpart[(size_t)SK * MROWS * XD]; // 25.2 MB
// chunked-scan chain state: layout [(b*NC + c) * DIM*NST + d*NST + n]
__device__ float g_scanP[(size_t)BATCH * NC * DIM * NST];  // 1.0 MB
__device__ float g_scanS[(size_t)BATCH * NC * DIM * NST];  // 1.0 MB
__device__ float g_scanI[(size_t)BATCH * NC * DIM * NST];  // 1.0 MB

// ---------------- helpers ----------------
__device__ __forceinline__ float softplusf(float x) {
    return (x > 20.f) ? x : log1pf(__expf(x));
}

__device__ __forceinline__ float siluf(float z) {
    return z * __fdividef(1.f, 1.f + __expf(-z));
}

__device__ __forceinline__ uint32_t smem_u32(const void* p) {
    uint32_t a;
    asm("{ .reg .u64 t; cvta.to.shared.u64 t, %1; cvt.u32.u64 %0, t; }"
        : "=r"(a) : "l"(p));
    return a;
}

// ---------------- fused fp16 convert pass (one launch for all operands) --------
#define CVT_N_X   (MROWS*DIM/4)         /* 1048576 */
#define CVT_N_WIN (2*DIM*DIM/4)         /*  524288 */
#define CVT_N_WOUT (DIM*DIM/4)          /*  262144 */
#define CVT_N_WDT (DIM*DTR/4)           /*   16384 */
#define CVT_TOTAL (CVT_N_X + CVT_N_WIN + CVT_N_WOUT + CVT_N_WDT)

__global__ void cvt_all_kernel(const float* __restrict__ x,    __half* __restrict__ xh,
                               const float* __restrict__ win,  __half* __restrict__ whin,
                               const float* __restrict__ wout, __half* __restrict__ whout,
                               const float* __restrict__ wdt,  __half* __restrict__ whdt)
{
    int i = blockIdx.x * blockDim.x + threadIdx.x;
    const float* src; __half* dst;
    if (i < CVT_N_X)                        { src = x;    dst = xh; }
    else if ((i -= CVT_N_X)   < CVT_N_WIN)  { src = win;  dst = whin; }
    else if ((i -= CVT_N_WIN) < CVT_N_WOUT) { src = wout; dst = whout; }
    else if ((i -= CVT_N_WOUT) < CVT_N_WDT) { src = wdt;  dst = whdt; }
    else return;
    float4 v = reinterpret_cast<const float4*>(src)[i];
    __half2 lo = __floats2half2_rn(v.x, v.y);
    __half2 hi = __floats2half2_rn(v.z, v.w);
    reinterpret_cast<__half2*>(dst)[2*i]   = lo;
    reinterpret_cast<__half2*>(dst)[2*i+1] = hi;
}

// =====================================================================
// cp.async-pipelined fp16 m16n8k16 GEMM: C = A(MxK) * B(NxK)^T.
// Operands in __half, K-contiguous. BM=128, BN=128, BK=64 halves
// (128B rows -> 8x16B chunks, XOR swizzle chunk^=row&7).
// 256 threads (8 warps), warp tile 64x32, 3-stage ring (32KB/stage),
// __launch_bounds__(256,2) -> 2 CTAs/SM (16 warps) for latency hiding.
// ACT: 0 = C fp32
//      1 = Ch fp16 = softplus(acc + bias[n])            (delta)
//      2 = n<DIM: C fp32 (xcin) ; n>=DIM: Ch fp16 = silu (gate)
// =====================================================================
#define GEMM_SMEM (3*32768)

template<int ACT>
__global__ void __launch_bounds__(256, 2)
gemm_h(const __half* __restrict__ A, int lda,
       const __half* __restrict__ Bm, int ldb,
       float* __restrict__ C, int ldc,
       __half* __restrict__ Ch,
       const float* __restrict__ bias, int K)
{
    extern __shared__ __align__(128) uint32_t sm[];
    const uint32_t sbase = smem_u32(sm);

    const int tid  = threadIdx.x;
    const int wid  = tid >> 5;
    const int lane = tid & 31;
    const int g    = lane >> 2;
    const int tig  = lane & 3;
    const int wm   = (wid >> 2) * 64;   // 2 warp rows over 128
    const int wn   = (wid & 3) * 32;    // 4 warp cols over 128
    const int m0   = blockIdx.y * 128;
    const int n0   = blockIdx.x * 128;

    const int rb    = tid >> 3;        // 0..31
    const int chk   = tid & 7;
    const uint32_t cxoff = (uint32_t)((chk ^ (rb & 7)) << 4);
    const __half* gA0 = A  + (size_t)(m0 + rb) * lda + chk * 8;
    const __half* gB0 = Bm + (size_t)(n0 + rb) * ldb + chk * 8;
    const uint32_t sOff = rb * 128 + cxoff;

    const int T = K >> 6;

    auto issue_tile = [&](int t) {
        const int stage = t % 3;
        const int k0 = t << 6;
        const uint32_t sA = sbase + stage * 32768 + sOff;
        const uint32_t sB = sA + 16384;
        const __half* gA = gA0 + k0;
        const __half* gB = gB0 + k0;
#pragma unroll
        for (int i = 0; i < 4; i++)   // A: 128 rows
            asm volatile("cp.async.cg.shared.global [%0], [%1], 16;"
                         :: "r"(sA + i * 4096), "l"(gA + (size_t)32 * i * lda));
#pragma unroll
        for (int i = 0; i < 4; i++)   // B: 128 rows
            asm volatile("cp.async.cg.shared.global [%0], [%1], 16;"
                         :: "r"(sB + i * 4096), "l"(gB + (size_t)32 * i * ldb));
        asm volatile("cp.async.commit_group;" ::: "memory");
    };

    float c[4][4][4];
#pragma unroll
    for (int i = 0; i < 4; i++)
#pragma unroll
        for (int j = 0; j < 4; j++)
#pragma unroll
            for (int r = 0; r < 4; r++) c[i][j][r] = 0.f;

    const int rrA = ((lane >> 3) & 1) * 8 + (lane & 7);
    const int khA = lane >> 4;
    const int rrB = lane & 7;
    const int khB = (lane >> 3) & 1;

    auto compute = [&](int stage) {
        const uint32_t Abase = sbase + stage * 32768;
        const uint32_t Bbase = Abase + 16384;
#pragma unroll
        for (int ks = 0; ks < 4; ks++) {
            const int c0 = 2 * ks;
            uint32_t a[4][4], b[4][2];
#pragma unroll
            for (int mt = 0; mt < 4; mt++) {
                const int row = wm + mt * 16 + rrA;
                const uint32_t addr = Abase + row * 128
                                    + (((c0 + khA) ^ (row & 7)) << 4);
                asm volatile(
                    "ldmatrix.sync.aligned.m8n8.x4.shared.b16 {%0,%1,%2,%3}, [%4];"
                    : "=r"(a[mt][0]), "=r"(a[mt][1]), "=r"(a[mt][2]), "=r"(a[mt][3])
                    : "r"(addr));
            }
#pragma unroll
            for (int nt = 0; nt < 4; nt++) {
                const int row = wn + nt * 8 + rrB;
                const uint32_t addr = Bbase + row * 128
                                    + (((c0 + khB) ^ (row & 7)) << 4);
                asm volatile(
                    "ldmatrix.sync.aligned.m8n8.x2.shared.b16 {%0,%1}, [%2];"
                    : "=r"(b[nt][0]), "=r"(b[nt][1])
                    : "r"(addr));
            }
#pragma unroll
            for (int mt = 0; mt < 4; mt++)
#pragma unroll
                for (int nt = 0; nt < 4; nt++) {
                    asm volatile(
                        "mma.sync.aligned.m16n8k16.row.col.f32.f16.f16.f32 "
                        "{%0,%1,%2,%3}, {%4,%5,%6,%7}, {%8,%9}, {%0,%1,%2,%3};\n"
                        : "+f"(c[mt][nt][0]), "+f"(c[mt][nt][1]),
                          "+f"(c[mt][nt][2]), "+f"(c[mt][nt][3])
                        : "r"(a[mt][0]), "r"(a[mt][1]), "r"(a[mt][2]), "r"(a[mt][3]),
                          "r"(b[nt][0]), "r"(b[nt][1]));
                }
        }
    };

    issue_tile(0);
    if (T > 1) issue_tile(1);

    for (int t = 0; t < T; ++t) {
        if (t + 2 < T) {
            issue_tile(t + 2);
            asm volatile("cp.async.wait_group 2;" ::: "memory");
        } else {
            asm volatile("cp.async.wait_group 0;" ::: "memory");
        }
        __syncthreads();
        compute(t % 3);
        __syncthreads();
    }

    // ---- epilogue ----
#pragma unroll
    for (int mt = 0; mt < 4; mt++) {
        int r = m0 + wm + mt * 16 + g;
#pragma unroll
        for (int nt = 0; nt < 4; nt++) {
            int n = n0 + wn + nt * 8 + tig * 2;
            float v0 = c[mt][nt][0], v1 = c[mt][nt][1];
            float v2 = c[mt][nt][2], v3 = c[mt][nt][3];
            if (ACT == 0) {
                *reinterpret_cast<float2*>(C + (size_t)r * ldc + n)       = make_float2(v0, v1);
                *reinterpret_cast<float2*>(C + (size_t)(r + 8) * ldc + n) = make_float2(v2, v3);
            } else if (ACT == 1) {
                float b0 = bias[n], b1 = bias[n + 1];
                *reinterpret_cast<__half2*>(Ch + (size_t)r * ldc + n) =
                    __floats2half2_rn(softplusf(v0 + b0), softplusf(v1 + b1));
                *reinterpret_cast<__half2*>(Ch + (size_t)(r + 8) * ldc + n) =
                    __floats2half2_rn(softplusf(v2 + b0), softplusf(v3 + b1));
            } else { // ACT == 2: split xz
                if (n < DIM) {
                    *reinterpret_cast<float2*>(C + (size_t)r * DIM + n)       = make_float2(v0, v1);
                    *reinterpret_cast<float2*>(C + (size_t)(r + 8) * DIM + n) = make_float2(v2, v3);
                } else {
                    int nz = n - DIM;
                    *reinterpret_cast<__half2*>(Ch + (size_t)r * DIM + nz) =
                        __floats2half2_rn(siluf(v0), siluf(v1));
                    *reinterpret_cast<__half2*>(Ch + (size_t)(r + 8) * DIM + nz) =
                        __floats2half2_rn(siluf(v2), siluf(v3));
                }
            }
        }
    }
}

// =====================================================================
// x_proj split-K FFMA GEMM (exact fp32, R11 tile): part[sk] +=
// xc(64 rows) @ W[96,K]^T over K-slice sk (KS=64). Tile 64x96,
// 128 threads (TM=8, TN=6), BK=16. grid = (SK, M/64).
// =====================================================================
__global__ void __launch_bounds__(128)
xproj_splitk(const float* __restrict__ A,     // xc [M, DIM]
             const float* __restrict__ Bm,    // x_proj_w [XD, DIM]
             float* __restrict__ part)        // [SK, M, XD]
{
    constexpr int KS = DIM / SK;   // 64 k per split
    __shared__ float As[16][64];
    __shared__ float Bs[16][XD];

    const int tid = threadIdx.x;
    const int tx  = tid & 15;      // 16 col groups of 6
    const int ty  = tid >> 4;      // 8 row groups of 8
    const int m0  = blockIdx.y * 64;
    const int kbase = blockIdx.x * KS;

    float acc[8][6];
#pragma unroll
    for (int i = 0; i < 8; i++)
#pragma unroll
        for (int j = 0; j < 6; j++) acc[i][j] = 0.f;

    for (int kt = 0; kt < KS; kt += 16) {
        const int k0 = kbase + kt;
#pragma unroll
        for (int it = 0; it < 2; it++) {
            int s = tid + it * 128;
            int row = s >> 2;
            int kk  = (s & 3) * 4;
            float4 v = *reinterpret_cast<const float4*>(
                A + (size_t)(m0 + row) * DIM + k0 + kk);
            As[kk+0][row] = v.x; As[kk+1][row] = v.y;
            As[kk+2][row] = v.z; As[kk+3][row] = v.w;
        }
#pragma unroll
        for (int it = 0; it < 3; it++) {
            int s = tid + it * 128;
            int row = s >> 2;
            int kk  = (s & 3) * 4;
            float4 v = *reinterpret_cast<const float4*>(
                Bm + (size_t)row * DIM + k0 + kk);
            Bs[kk+0][row] = v.x; Bs[kk+1][row] = v.y;
            Bs[kk+2][row] = v.z; Bs[kk+3][row] = v.w;
        }
        __syncthreads();

#pragma unroll
        for (int kk = 0; kk < 16; kk++) {
            float a[8], b[6];
            *reinterpret_cast<float4*>(&a[0]) =
                *reinterpret_cast<const float4*>(&As[kk][ty*8]);
            *reinterpret_cast<float4*>(&a[4]) =
                *reinterpret_cast<const float4*>(&As[kk][ty*8 + 4]);
#pragma unroll
            for (int j = 0; j < 6; j++) b[j] = Bs[kk][tx*6 + j];
#pragma unroll
            for (int i = 0; i < 8; i++)
#pragma unroll
                for (int j = 0; j < 6; j++)
                    acc[i][j] = fmaf(a[i], b[j], acc[i][j]);
        }
        __syncthreads();
    }

    float* dst = part + (size_t)blockIdx.x * MROWS * XD;
#pragma unroll
    for (int i = 0; i < 8; i++) {
        const size_t r = (size_t)(m0 + ty*8 + i) * XD + tx*6;
#pragma unroll
        for (int j = 0; j < 6; j++)
            dst[r + j] = acc[i][j];
    }
}

// reduce SK partials -> xdbl; fused dtin (fp16-rounded first 64 cols)
__global__ void __launch_bounds__(256)
xproj_reduce(const float* __restrict__ part,
             float* __restrict__ xdbl,
             __half* __restrict__ dtin)
{
    int i = blockIdx.x * blockDim.x + threadIdx.x;   // over MROWS*XD
    if (i >= MROWS * XD) return;
    float s = 0.f;
#pragma unroll
    for (int sk = 0; sk < SK; sk++)
        s += part[(size_t)sk * MROWS * XD + i];
    xdbl[i] = s;
    int n = i % XD;
    if (n < DTR) {
        int m = i / XD;
        dtin[(size_t)m * DTR + n] = __float2half_rn(s);
    }
}

// ---------------- depthwise conv1d k=3 pad=1 (dense xcin input) ----------------
// Emits fp32 xc (x_proj) and fp16 xch (scan).
__global__ void conv_kernel(const float* __restrict__ xcin,
                            const float* __restrict__ w,
                            const float* __restrict__ bconv,
                            float* __restrict__ xc,
                            __half* __restrict__ xch)
{
    int idx = blockIdx.x * blockDim.x + threadIdx.x;   // over MROWS*DIM
    if (idx >= MROWS * DIM) return;
    int d = idx & (DIM - 1);
    int l = (idx >> 10) & (SEQ - 1);
    const float* base = xcin + idx;
    float w0 = w[d*3+0], w1 = w[d*3+1], w2 = w[d*3+2];
    float acc = bconv[d];
    if (l > 0)       acc = fmaf(w0, base[-DIM], acc);
    acc = fmaf(w1, base[0], acc);
    if (l < SEQ - 1) acc = fmaf(w2, base[DIM], acc);
    xc[idx] = acc;
    xch[idx] = __float2half_rn(acc);
}

// =====================================================================
// Chunked selective scan (3 passes; recurrence is linear -> exact).
// Warp = 2 channels x 16 states. Lanes 0-15: chan0; 16-31: chan1.
// delta/u read fp16; B/C read fp32 from xdbl; gate read fp16.
// =====================================================================

// Pass A: per-chunk P = prod dA and zero-init partial state S
__global__ void __launch_bounds__(256)
scan_part(const __half* __restrict__ delta,
          const __half* __restrict__ u,
          const float* __restrict__ xdbl,
          const float* __restrict__ A_log,
          float* __restrict__ Pout,
          float* __restrict__ Sout)
{
    const int lane = threadIdx.x & 31;
    const int warp = threadIdx.x >> 5;
    const int n = lane & 15;
    const int chan = blockIdx.x * 16 + (warp << 1) + (lane >> 4);
    const int b = chan >> 10;
    const int d = chan & (DIM - 1);
    const int c = blockIdx.y;

    const float A = -__expf(__ldg(A_log + d*NST + n));

    const size_t row0 = (size_t)b * SEQ + (size_t)c * LC;
    const __half* pD = delta + row0 * DIM + d;
    const __half* pU = u     + row0 * DIM + d;
    const float* pBC = xdbl  + row0 * XD + DTR + n;

    float s = 0.f, P = 1.f;
#pragma unroll 4
    for (int t = 0; t < LC; ++t) {
        float dt = __half2float(__ldg(pD));
        float uu = __half2float(__ldg(pU));
        float Bn = __ldg(pBC);
        float dA = __expf(dt * A);
        s = fmaf(dA, s, dt * Bn * uu);
        P *= dA;
        pD += DIM; pU += DIM; pBC += XD;
    }
    const size_t o = (((size_t)b * NC + c) * DIM + d) * NST + n;
    Pout[o] = P;
    Sout[o] = s;
}

// Pass B: sequential chain over chunks -> exact initial state per chunk
__global__ void __launch_bounds__(256)
scan_chain(const float* __restrict__ P,
           const float* __restrict__ S,
           float* __restrict__ I)
{
    const int tid = blockIdx.x * blockDim.x + threadIdx.x;  // 0..32767
    const int b = tid >> 14;            // / (DIM*NST)
    const int rest = tid & 16383;       // d*NST + n
    float s = 0.f;
#pragma unroll
    for (int c = 0; c < NC; ++c) {
        const size_t o = (((size_t)b * NC + c) << 14) + rest;
        I[o] = s;
        s = fmaf(P[o], s, S[o]);
    }
}

// Pass C: re-run each chunk from its initial state, emit gated y (fp16)
__global__ void __launch_bounds__(256)
scan_emit(const __half* __restrict__ delta,
          const __half* __restrict__ u,
          const float* __restrict__ xdbl,
          const __half* __restrict__ gate,
          const float* __restrict__ A_log,
          const float* __restrict__ Dp,
          const float* __restrict__ I,
          __half* __restrict__ yg)
{
    const int lane = threadIdx.x & 31;
    const int warp = threadIdx.x >> 5;
    const int n = lane & 15;
    const int chan = blockIdx.x * 16 + (warp << 1) + (lane >> 4);
    const int b = chan >> 10;
    const int d = chan & (DIM - 1);
    const int c = blockIdx.y;

    const float A    = -__expf(__ldg(A_log + d*NST + n));
    const float Dpar = __ldg(Dp + d);

    const size_t row0 = (size_t)b * SEQ + (size_t)c * LC;
    const __half* pD = delta + row0 * DIM + d;
    const __half* pU = u     + row0 * DIM + d;
    const float* pBC = xdbl  + row0 * XD;
    const __half* pG = gate  + row0 * DIM + d;
    __half*      pY  = yg    + row0 * DIM + d;

    float s = I[(((size_t)b * NC + c) * DIM + d) * NST + n];

#pragma unroll 2
    for (int t = 0; t < LC; ++t) {
        float dt = __half2float(__ldg(pD));
        float uu = __half2float(__ldg(pU));
        float Bn = __ldg(pBC + DTR + n);
        float Cn = __ldg(pBC + DTR + NST + n);

        float dA = __expf(dt * A);
        s = fmaf(dA, s, dt * Bn * uu);

        float p = s * Cn;
        p += __shfl_xor_sync(0xffffffffu, p, 1);
        p += __shfl_xor_sync(0xffffffffu, p, 2);
        p += __shfl_xor_sync(0xffffffffu, p, 4);
        p += __shfl_xor_sync(0xffffffffu, p, 8);

        if (n == 0) {
            float gt = __half2float(__ldg(pG));
            float val = fmaf(uu, Dpar, p) * gt;
            pY[0] = __float2half_rn(val);
        }
        pD += DIM; pU += DIM; pBC += XD; pG += DIM; pY += DIM;
    }
}

// ---------------- launcher ----------------
extern "C" void kernel_launch(void* const* d_in, const int* in_sizes, int n_in,
                              void* d_out, int out_size)
{
    const float* x          = (const float*)d_in[0];
    const float* in_proj_w  = (const float*)d_in[1];
    const float* conv_w     = (const float*)d_in[2];
    const float* conv_b     = (const float*)d_in[3];
    const float* A_log      = (const float*)d_in[4];
    const float* D_param    = (const float*)d_in[5];
    const float* x_proj_w   = (const float*)d_in[6];
    const float* dt_proj_w  = (const float*)d_in[7];
    const float* dt_proj_b  = (const float*)d_in[8];
    const float* out_proj_w = (const float*)d_in[9];
    float* out = (float*)d_out;

    float *xcin, *xc, *xdbl, *xpart, *sP, *sS, *sI;
    __half *gate, *xch, *deltah, *xh, *whin, *whout, *whdt, *dtin, *ygh;
    cudaGetSymbolAddress((void**)&xcin,  g_xcin);
    cudaGetSymbolAddress((void**)&gate,  g_gate);
    cudaGetSymbolAddress((void**)&xc,    g_xc);
    cudaGetSymbolAddress((void**)&xch,   g_xch);
    cudaGetSymbolAddress((void**)&xdbl,  g_xdbl);
    cudaGetSymbolAddress((void**)&deltah,g_deltah);
    cudaGetSymbolAddress((void**)&xh,    g_xh);
    cudaGetSymbolAddress((void**)&whin,  g_wh_in);
    cudaGetSymbolAddress((void**)&whout, g_wh_out);
    cudaGetSymbolAddress((void**)&whdt,  g_wh_dt);
    cudaGetSymbolAddress((void**)&dtin,  g_dtin);
    cudaGetSymbolAddress((void**)&ygh,   g_ygh);
    cudaGetSymbolAddress((void**)&xpart, g_xpart);
    cudaGetSymbolAddress((void**)&sP,    g_scanP);
    cudaGetSymbolAddress((void**)&sS,    g_scanS);
    cudaGetSymbolAddress((void**)&sI,    g_scanI);

    const int M = MROWS;

    cudaFuncSetAttribute(gemm_h<0>, cudaFuncAttributeMaxDynamicSharedMemorySize, GEMM_SMEM);
    cudaFuncSetAttribute(gemm_h<1>, cudaFuncAttributeMaxDynamicSharedMemorySize, GEMM_SMEM);
    cudaFuncSetAttribute(gemm_h<2>, cudaFuncAttributeMaxDynamicSharedMemorySize, GEMM_SMEM);

    // 0. fp16-round all GEMM operands (single fused bandwidth pass)
    cvt_all_kernel<<<(CVT_TOTAL + 255)/256, 256>>>(
        x, xh, in_proj_w, whin, out_proj_w, whout, dt_proj_w, whdt);

    // 1. in_proj (split epilogue): xcin fp32 + pre-gated silu(z) fp16
    gemm_h<2><<<dim3((2*DIM)/128, M/128), 256, GEMM_SMEM>>>(
        xh, DIM, whin, DIM, xcin, DIM, gate, nullptr, DIM);

    // 2. depthwise conv1d -> xc (fp32) + xch (fp16)
    conv_kernel<<<(M*DIM)/256, 256>>>(xcin, conv_w, conv_b, xc, xch);

    // 3. x_proj split-K (exact fp32): partials then reduce (+fused dtin emit)
    xproj_splitk<<<dim3(SK, M/64), 128>>>(xc, x_proj_w, xpart);
    xproj_reduce<<<(M*XD + 255)/256, 256>>>(xpart, xdbl, dtin);

    // 4. dt_proj + softplus -> fp16 delta
    gemm_h<1><<<dim3(DIM/128, M/128), 256, GEMM_SMEM>>>(
        dtin, DTR, whdt, DTR, nullptr, DIM, deltah, dt_proj_b, DTR);

    // 5. chunked selective scan (parallelism x8 over time chunks)
    scan_part<<<dim3((BATCH*DIM)/16, NC), 256>>>(deltah, xch, xdbl, A_log, sP, sS);
    scan_chain<<<(BATCH*DIM*NST)/256, 256>>>(sP, sS, sI);
    scan_emit<<<dim3((BATCH*DIM)/16, NC), 256>>>(deltah, xch, xdbl, gate, A_log,
                                                 D_param, sI, ygh);

    // 6. out_proj: out = yg @ out_proj_w^T  (4096 x 1024 x 1024)
    gemm_h<0><<<dim3(DIM/128, M/128), 256, GEMM_SMEM>>>(
        ygh, DIM, whout, DIM, out, DIM, nullptr, nullptr, DIM);
}

// round 16
// speedup vs baseline: 1.0887x; 1.0887x over previous
#include <cuda_runtime.h>
#include <cuda_fp16.h>
#include <cstdint>

#define BATCH 2
#define SEQ   2048
#define DIM   1024
#define NST   16
#define DTR   64
#define XD    96   /* dt_rank + 2*N */

#define MROWS (BATCH*SEQ) /* 4096 */

#define NC 8      /* scan chunks */
#define LC 256    /* chunk length = SEQ/NC */

#define SK 16     /* x_proj split-K factor (KS = 64) */

// ---------------- scratch (allocation-free: __device__ globals) ----------------
__device__ float  g_xcin[(size_t)MROWS * DIM];    // 16.8 MB (in_proj xc-half, pre-conv)
__device__ __half g_gate[(size_t)MROWS * DIM];    // 8.4 MB  (silu(z), fp16)
__device__ __half g_xch[(size_t)MROWS * DIM];     // 8.4 MB  (conv out fp16: scan + x_proj)
__device__ float  g_xdbl[(size_t)MROWS * XD];     // 1.6 MB
__device__ __half g_deltah[(size_t)MROWS * DIM];  // 8.4 MB  (fp16 delta)
// fp16 GEMM operands
__device__ __half g_xh[(size_t)MROWS * DIM];      // 8.4 MB
__device__ __half g_wh_in[(size_t)2 * DIM * DIM]; // 4.2 MB
__device__ __half g_wh_out[(size_t)DIM * DIM];    // 2.1 MB
__device__ __half g_wh_dt[(size_t)DIM * DTR];     // 0.13 MB
__device__ __half g_wh_xp[(size_t)XD * DIM];      // 0.2 MB  (x_proj_w fp16)
__device__ __half g_dtin[(size_t)MROWS * DTR];    // 0.5 MB
__device__ __half g_ygh[(size_t)MROWS * DIM];     // 8.4 MB
// x_proj split-K partials
__device__ float g_xpart[(size_t)SK * MROWS * XD]; // 25.2 MB
// chunked-scan chain state: layout [(b*NC + c) * DIM*NST + d*NST + n]
__device__ float g_scanP[(size_t)BATCH * NC * DIM * NST];  // 1.0 MB
__device__ float g_scanS[(size_t)BATCH * NC * DIM * NST];  // 1.0 MB
__device__ float g_scanI[(size_t)BATCH * NC * DIM * NST];  // 1.0 MB

// ---------------- helpers ----------------
__device__ __forceinline__ float softplusf(float x) {
    return (x > 20.f) ? x : log1pf(__expf(x));
}

__device__ __forceinline__ float siluf(float z) {
    return z * __fdividef(1.f, 1.f + __expf(-z));
}

__device__ __forceinline__ uint32_t smem_u32(const void* p) {
    uint32_t a;
    asm("{ .reg .u64 t; cvta.to.shared.u64 t, %1; cvt.u32.u64 %0, t; }"
        : "=r"(a) : "l"(p));
    return a;
}

// ---------------- fused fp16 convert pass (one launch for all operands) --------
#define CVT_N_X    (MROWS*DIM/4)        /* 1048576 */
#define CVT_N_WIN  (2*DIM*DIM/4)        /*  524288 */
#define CVT_N_WOUT (DIM*DIM/4)          /*  262144 */
#define CVT_N_WDT  (DIM*DTR/4)          /*   16384 */
#define CVT_N_WXP  (XD*DIM/4)           /*   24576 */
#define CVT_TOTAL  (CVT_N_X + CVT_N_WIN + CVT_N_WOUT + CVT_N_WDT + CVT_N_WXP)

__global__ void cvt_all_kernel(const float* __restrict__ x,    __half* __restrict__ xh,
                               const float* __restrict__ win,  __half* __restrict__ whin,
                               const float* __restrict__ wout, __half* __restrict__ whout,
                               const float* __restrict__ wdt,  __half* __restrict__ whdt,
                               const float* __restrict__ wxp,  __half* __restrict__ whxp)
{
    int i = blockIdx.x * blockDim.x + threadIdx.x;
    const float* src; __half* dst;
    if (i < CVT_N_X)                        { src = x;    dst = xh; }
    else if ((i -= CVT_N_X)   < CVT_N_WIN)  { src = win;  dst = whin; }
    else if ((i -= CVT_N_WIN) < CVT_N_WOUT) { src = wout; dst = whout; }
    else if ((i -= CVT_N_WOUT) < CVT_N_WDT) { src = wdt;  dst = whdt; }
    else if ((i -= CVT_N_WDT) < CVT_N_WXP)  { src = wxp;  dst = whxp; }
    else return;
    float4 v = reinterpret_cast<const float4*>(src)[i];
    __half2 lo = __floats2half2_rn(v.x, v.y);
    __half2 hi = __floats2half2_rn(v.z, v.w);
    reinterpret_cast<__half2*>(dst)[2*i]   = lo;
    reinterpret_cast<__half2*>(dst)[2*i+1] = hi;
}

// =====================================================================
// cp.async-pipelined fp16 m16n8k16 GEMM: C = A(MxK) * B(NxK)^T.
// Operands in __half, K-contiguous. BM=128, BN=128, BK=64 halves
// (128B rows -> 8x16B chunks, XOR swizzle chunk^=row&7).
// 256 threads (8 warps), warp tile 64x32, 3-stage ring (32KB/stage),
// __launch_bounds__(256,2) -> 2 CTAs/SM (16 warps) for latency hiding.
// ACT: 0 = C fp32
//      1 = Ch fp16 = softplus(acc + bias[n])            (delta)
//      2 = n<DIM: C fp32 (xcin) ; n>=DIM: Ch fp16 = silu (gate)
// =====================================================================
#define GEMM_SMEM (3*32768)

template<int ACT>
__global__ void __launch_bounds__(256, 2)
gemm_h(const __half* __restrict__ A, int lda,
       const __half* __restrict__ Bm, int ldb,
       float* __restrict__ C, int ldc,
       __half* __restrict__ Ch,
       const float* __restrict__ bias, int K)
{
    extern __shared__ __align__(128) uint32_t sm[];
    const uint32_t sbase = smem_u32(sm);

    const int tid  = threadIdx.x;
    const int wid  = tid >> 5;
    const int lane = tid & 31;
    const int g    = lane >> 2;
    const int tig  = lane & 3;
    const int wm   = (wid >> 2) * 64;   // 2 warp rows over 128
    const int wn   = (wid & 3) * 32;    // 4 warp cols over 128
    const int m0   = blockIdx.y * 128;
    const int n0   = blockIdx.x * 128;

    const int rb    = tid >> 3;        // 0..31
    const int chk   = tid & 7;
    const uint32_t cxoff = (uint32_t)((chk ^ (rb & 7)) << 4);
    const __half* gA0 = A  + (size_t)(m0 + rb) * lda + chk * 8;
    const __half* gB0 = Bm + (size_t)(n0 + rb) * ldb + chk * 8;
    const uint32_t sOff = rb * 128 + cxoff;

    const int T = K >> 6;

    auto issue_tile = [&](int t) {
        const int stage = t % 3;
        const int k0 = t << 6;
        const uint32_t sA = sbase + stage * 32768 + sOff;
        const uint32_t sB = sA + 16384;
        const __half* gA = gA0 + k0;
        const __half* gB = gB0 + k0;
#pragma unroll
        for (int i = 0; i < 4; i++)   // A: 128 rows
            asm volatile("cp.async.cg.shared.global [%0], [%1], 16;"
                         :: "r"(sA + i * 4096), "l"(gA + (size_t)32 * i * lda));
#pragma unroll
        for (int i = 0; i < 4; i++)   // B: 128 rows
            asm volatile("cp.async.cg.shared.global [%0], [%1], 16;"
                         :: "r"(sB + i * 4096), "l"(gB + (size_t)32 * i * ldb));
        asm volatile("cp.async.commit_group;" ::: "memory");
    };

    float c[4][4][4];
#pragma unroll
    for (int i = 0; i < 4; i++)
#pragma unroll
        for (int j = 0; j < 4; j++)
#pragma unroll
            for (int r = 0; r < 4; r++) c[i][j][r] = 0.f;

    const int rrA = ((lane >> 3) & 1) * 8 + (lane & 7);
    const int khA = lane >> 4;
    const int rrB = lane & 7;
    const int khB = (lane >> 3) & 1;

    auto compute = [&](int stage) {
        const uint32_t Abase = sbase + stage * 32768;
        const uint32_t Bbase = Abase + 16384;
#pragma unroll
        for (int ks = 0; ks < 4; ks++) {
            const int c0 = 2 * ks;
            uint32_t a[4][4], b[4][2];
#pragma unroll
            for (int mt = 0; mt < 4; mt++) {
                const int row = wm + mt * 16 + rrA;
                const uint32_t addr = Abase + row * 128
                                    + (((c0 + khA) ^ (row & 7)) << 4);
                asm volatile(
                    "ldmatrix.sync.aligned.m8n8.x4.shared.b16 {%0,%1,%2,%3}, [%4];"
                    : "=r"(a[mt][0]), "=r"(a[mt][1]), "=r"(a[mt][2]), "=r"(a[mt][3])
                    : "r"(addr));
            }
#pragma unroll
            for (int nt = 0; nt < 4; nt++) {
                const int row = wn + nt * 8 + rrB;
                const uint32_t addr = Bbase + row * 128
                                    + (((c0 + khB) ^ (row & 7)) << 4);
                asm volatile(
                    "ldmatrix.sync.aligned.m8n8.x2.shared.b16 {%0,%1}, [%2];"
                    : "=r"(b[nt][0]), "=r"(b[nt][1])
                    : "r"(addr));
            }
#pragma unroll
            for (int mt = 0; mt < 4; mt++)
#pragma unroll
                for (int nt = 0; nt < 4; nt++) {
                    asm volatile(
                        "mma.sync.aligned.m16n8k16.row.col.f32.f16.f16.f32 "
                        "{%0,%1,%2,%3}, {%4,%5,%6,%7}, {%8,%9}, {%0,%1,%2,%3};\n"
                        : "+f"(c[mt][nt][0]), "+f"(c[mt][nt][1]),
                          "+f"(c[mt][nt][2]), "+f"(c[mt][nt][3])
                        : "r"(a[mt][0]), "r"(a[mt][1]), "r"(a[mt][2]), "r"(a[mt][3]),
                          "r"(b[nt][0]), "r"(b[nt][1]));
                }
        }
    };

    issue_tile(0);
    if (T > 1) issue_tile(1);

    for (int t = 0; t < T; ++t) {
        if (t + 2 < T) {
            issue_tile(t + 2);
            asm volatile("cp.async.wait_group 2;" ::: "memory");
        } else {
            asm volatile("cp.async.wait_group 0;" ::: "memory");
        }
        __syncthreads();
        compute(t % 3);
        __syncthreads();
    }

    // ---- epilogue ----
#pragma unroll
    for (int mt = 0; mt < 4; mt++) {
        int r = m0 + wm + mt * 16 + g;
#pragma unroll
        for (int nt = 0; nt < 4; nt++) {
            int n = n0 + wn + nt * 8 + tig * 2;
            float v0 = c[mt][nt][0], v1 = c[mt][nt][1];
            float v2 = c[mt][nt][2], v3 = c[mt][nt][3];
            if (ACT == 0) {
                *reinterpret_cast<float2*>(C + (size_t)r * ldc + n)       = make_float2(v0, v1);
                *reinterpret_cast<float2*>(C + (size_t)(r + 8) * ldc + n) = make_float2(v2, v3);
            } else if (ACT == 1) {
                float b0 = bias[n], b1 = bias[n + 1];
                *reinterpret_cast<__half2*>(Ch + (size_t)r * ldc + n) =
                    __floats2half2_rn(softplusf(v0 + b0), softplusf(v1 + b1));
                *reinterpret_cast<__half2*>(Ch + (size_t)(r + 8) * ldc + n) =
                    __floats2half2_rn(softplusf(v2 + b0), softplusf(v3 + b1));
            } else { // ACT == 2: split xz
                if (n < DIM) {
                    *reinterpret_cast<float2*>(C + (size_t)r * DIM + n)       = make_float2(v0, v1);
                    *reinterpret_cast<float2*>(C + (size_t)(r + 8) * DIM + n) = make_float2(v2, v3);
                } else {
                    int nz = n - DIM;
                    *reinterpret_cast<__half2*>(Ch + (size_t)r * DIM + nz) =
                        __floats2half2_rn(siluf(v0), siluf(v1));
                    *reinterpret_cast<__half2*>(Ch + (size_t)(r + 8) * DIM + nz) =
                        __floats2half2_rn(siluf(v2), siluf(v3));
                }
            }
        }
    }
}

// =====================================================================
// x_proj split-K fp16 MMA: part[sk] = xch(128 rows) @ W[96, K]^T over
// K-slice sk (KS = 64 halves). One 128x96x64 tile per CTA: single
// cp.async load, 4 k16-steps, 8 warps (warp tile 64x24). fp32 partials.
// grid = (SK, M/128). Then xproj_reduce sums -> xdbl + dtin(fp16).
// =====================================================================
__global__ void __launch_bounds__(256)
xproj_mma(const __half* __restrict__ A,      // xch [M, DIM]
          const __half* __restrict__ W,      // x_proj_w fp16 [XD, DIM]
          float* __restrict__ part)          // [SK, M, XD]
{
    __shared__ __align__(128) uint8_t smb[28672];   // A 16KB + B 12KB
    const uint32_t sbase = smem_u32(smb);

    const int tid  = threadIdx.x;
    const int wid  = tid >> 5;
    const int lane = tid & 31;
    const int g    = lane >> 2;
    const int tig  = lane & 3;
    const int wm   = (wid >> 2) * 64;   // 2 warp rows over 128
    const int wn   = (wid & 3) * 24;    // 4 warp cols over 96
    const int m0   = blockIdx.y * 128;
    const int k0   = blockIdx.x * 64;   // K-slice start (halves)

    const int rb  = tid >> 3;           // 0..31
    const int chk = tid & 7;
    const uint32_t cxoff = (uint32_t)((chk ^ (rb & 7)) << 4);
    const uint32_t sOff = rb * 128 + cxoff;

    // A: 128 rows, B: 96 rows (3 x 32)
    const __half* gA = A + (size_t)(m0 + rb) * DIM + k0 + chk * 8;
    const __half* gB = W + (size_t)rb * DIM + k0 + chk * 8;
#pragma unroll
    for (int i = 0; i < 4; i++)
        asm volatile("cp.async.cg.shared.global [%0], [%1], 16;"
                     :: "r"(sbase + sOff + i * 4096), "l"(gA + (size_t)32 * i * DIM));
#pragma unroll
    for (int i = 0; i < 3; i++)
        asm volatile("cp.async.cg.shared.global [%0], [%1], 16;"
                     :: "r"(sbase + 16384 + sOff + i * 4096), "l"(gB + (size_t)32 * i * DIM));
    asm volatile("cp.async.commit_group;" ::: "memory");
    asm volatile("cp.async.wait_group 0;" ::: "memory");
    __syncthreads();

    float c[4][3][4];
#pragma unroll
    for (int i = 0; i < 4; i++)
#pragma unroll
        for (int j = 0; j < 3; j++)
#pragma unroll
            for (int r = 0; r < 4; r++) c[i][j][r] = 0.f;

    const int rrA = ((lane >> 3) & 1) * 8 + (lane & 7);
    const int khA = lane >> 4;
    const int rrB = lane & 7;
    const int khB = (lane >> 3) & 1;

#pragma unroll
    for (int ks = 0; ks < 4; ks++) {
        const int c0 = 2 * ks;
        uint32_t a[4][4], b[3][2];
#pragma unroll
        for (int mt = 0; mt < 4; mt++) {
            const int row = wm + mt * 16 + rrA;
            const uint32_t addr = sbase + row * 128
                                + (((c0 + khA) ^ (row & 7)) << 4);
            asm volatile(
                "ldmatrix.sync.aligned.m8n8.x4.shared.b16 {%0,%1,%2,%3}, [%4];"
                : "=r"(a[mt][0]), "=r"(a[mt][1]), "=r"(a[mt][2]), "=r"(a[mt][3])
                : "r"(addr));
        }
#pragma unroll
        for (int nt = 0; nt < 3; nt++) {
            const int row = wn + nt * 8 + rrB;
            const uint32_t addr = sbase + 16384 + row * 128
                                + (((c0 + khB) ^ (row & 7)) << 4);
            asm volatile(
                "ldmatrix.sync.aligned.m8n8.x2.shared.b16 {%0,%1}, [%2];"
                : "=r"(b[nt][0]), "=r"(b[nt][1])
                : "r"(addr));
        }
#pragma unroll
        for (int mt = 0; mt < 4; mt++)
#pragma unroll
            for (int nt = 0; nt < 3; nt++) {
                asm volatile(
                    "mma.sync.aligned.m16n8k16.row.col.f32.f16.f16.f32 "
                    "{%0,%1,%2,%3}, {%4,%5,%6,%7}, {%8,%9}, {%0,%1,%2,%3};\n"
                    : "+f"(c[mt][nt][0]), "+f"(c[mt][nt][1]),
                      "+f"(c[mt][nt][2]), "+f"(c[mt][nt][3])
                    : "r"(a[mt][0]), "r"(a[mt][1]), "r"(a[mt][2]), "r"(a[mt][3]),
                      "r"(b[nt][0]), "r"(b[nt][1]));
            }
    }

    float* dst = part + (size_t)blockIdx.x * MROWS * XD;
#pragma unroll
    for (int mt = 0; mt < 4; mt++) {
        int r = m0 + wm + mt * 16 + g;
#pragma unroll
        for (int nt = 0; nt < 3; nt++) {
            int n = wn + nt * 8 + tig * 2;
            *reinterpret_cast<float2*>(dst + (size_t)r * XD + n) =
                make_float2(c[mt][nt][0], c[mt][nt][1]);
            *reinterpret_cast<float2*>(dst + (size_t)(r + 8) * XD + n) =
                make_float2(c[mt][nt][2], c[mt][nt][3]);
        }
    }
}

// reduce SK partials -> xdbl; fused dtin (fp16-rounded first 64 cols)
__global__ void __launch_bounds__(256)
xproj_reduce(const float* __restrict__ part,
             float* __restrict__ xdbl,
             __half* __restrict__ dtin)
{
    int i = blockIdx.x * blockDim.x + threadIdx.x;   // over MROWS*XD
    if (i >= MROWS * XD) return;
    float s = 0.f;
#pragma unroll
    for (int sk = 0; sk < SK; sk++)
        s += part[(size_t)sk * MROWS * XD + i];
    xdbl[i] = s;
    int n = i % XD;
    if (n < DTR) {
        int m = i / XD;
        dtin[(size_t)m * DTR + n] = __float2half_rn(s);
    }
}

// ---------------- depthwise conv1d k=3 pad=1 (dense xcin input) ----------------
// Emits fp16 xch (scan + x_proj).
__global__ void conv_kernel(const float* __restrict__ xcin,
                            const float* __restrict__ w,
                            const float* __restrict__ bconv,
                            __half* __restrict__ xch)
{
    int idx = blockIdx.x * blockDim.x + threadIdx.x;   // over MROWS*DIM
    if (idx >= MROWS * DIM) return;
    int d = idx & (DIM - 1);
    int l = (idx >> 10) & (SEQ - 1);
    const float* base = xcin + idx;
    float w0 = w[d*3+0], w1 = w[d*3+1], w2 = w[d*3+2];
    float acc = bconv[d];
    if (l > 0)       acc = fmaf(w0, base[-DIM], acc);
    acc = fmaf(w1, base[0], acc);
    if (l < SEQ - 1) acc = fmaf(w2, base[DIM], acc);
    xch[idx] = __float2half_rn(acc);
}

// =====================================================================
// Chunked selective scan (3 passes; recurrence is linear -> exact).
// Warp = 2 channels x 16 states. Lanes 0-15: chan0; 16-31: chan1.
// delta/u read fp16; B/C read fp32 from xdbl; gate read fp16.
// =====================================================================

// Pass A: per-chunk P = prod dA and zero-init partial state S
__global__ void __launch_bounds__(256)
scan_part(const __half* __restrict__ delta,
          const __half* __restrict__ u,
          const float* __restrict__ xdbl,
          const float* __restrict__ A_log,
          float* __restrict__ Pout,
          float* __restrict__ Sout)
{
    const int lane = threadIdx.x & 31;
    const int warp = threadIdx.x >> 5;
    const int n = lane & 15;
    const int chan = blockIdx.x * 16 + (warp << 1) + (lane >> 4);
    const int b = chan >> 10;
    const int d = chan & (DIM - 1);
    const int c = blockIdx.y;

    const float A = -__expf(__ldg(A_log + d*NST + n));

    const size_t row0 = (size_t)b * SEQ + (size_t)c * LC;
    const __half* pD = delta + row0 * DIM + d;
    const __half* pU = u     + row0 * DIM + d;
    const float* pBC = xdbl  + row0 * XD + DTR + n;

    float s = 0.f, P = 1.f;
#pragma unroll 4
    for (int t = 0; t < LC; ++t) {
        float dt = __half2float(__ldg(pD));
        float uu = __half2float(__ldg(pU));
        float Bn = __ldg(pBC);
        float dA = __expf(dt * A);
        s = fmaf(dA, s, dt * Bn * uu);
        P *= dA;
        pD += DIM; pU += DIM; pBC += XD;
    }
    const size_t o = (((size_t)b * NC + c) * DIM + d) * NST + n;
    Pout[o] = P;
    Sout[o] = s;
}

// Pass B: sequential chain over chunks -> exact initial state per chunk
__global__ void __launch_bounds__(256)
scan_chain(const float* __restrict__ P,
           const float* __restrict__ S,
           float* __restrict__ I)
{
    const int tid = blockIdx.x * blockDim.x + threadIdx.x;  // 0..32767
    const int b = tid >> 14;            // / (DIM*NST)
    const int rest = tid & 16383;       // d*NST + n
    float s = 0.f;
#pragma unroll
    for (int c = 0; c < NC; ++c) {
        const size_t o = (((size_t)b * NC + c) << 14) + rest;
        I[o] = s;
        s = fmaf(P[o], s, S[o]);
    }
}

// Pass C: re-run each chunk from its initial state, emit gated y (fp16)
__global__ void __launch_bounds__(256)
scan_emit(const __half* __restrict__ delta,
          const __half* __restrict__ u,
          const float* __restrict__ xdbl,
          const __half* __restrict__ gate,
          const float* __restrict__ A_log,
          const float* __restrict__ Dp,
          const float* __restrict__ I,
          __half* __restrict__ yg)
{
    const int lane = threadIdx.x & 31;
    const int warp = threadIdx.x >> 5;
    const int n = lane & 15;
    const int chan = blockIdx.x * 16 + (warp << 1) + (lane >> 4);
    const int b = chan >> 10;
    const int d = chan & (DIM - 1);
    const int c = blockIdx.y;

    const float A    = -__expf(__ldg(A_log + d*NST + n));
    const float Dpar = __ldg(Dp + d);

    const size_t row0 = (size_t)b * SEQ + (size_t)c * LC;
    const __half* pD = delta + row0 * DIM + d;
    const __half* pU = u     + row0 * DIM + d;
    const float* pBC = xdbl  + row0 * XD;
    const __half* pG = gate  + row0 * DIM + d;
    __half*      pY  = yg    + row0 * DIM + d;

    float s = I[(((size_t)b * NC + c) * DIM + d) * NST + n];

#pragma unroll 2
    for (int t = 0; t < LC; ++t) {
        float dt = __half2float(__ldg(pD));
        float uu = __half2float(__ldg(pU));
        float Bn = __ldg(pBC + DTR + n);
        float Cn = __ldg(pBC + DTR + NST + n);

        float dA = __expf(dt * A);
        s = fmaf(dA, s, dt * Bn * uu);

        float p = s * Cn;
        p += __shfl_xor_sync(0xffffffffu, p, 1);
        p += __shfl_xor_sync(0xffffffffu, p, 2);
        p += __shfl_xor_sync(0xffffffffu, p, 4);
        p += __shfl_xor_sync(0xffffffffu, p, 8);

        if (n == 0) {
            float gt = __half2float(__ldg(pG));
            float val = fmaf(uu, Dpar, p) * gt;
            pY[0] = __float2half_rn(val);
        }
        pD += DIM; pU += DIM; pBC += XD; pG += DIM; pY += DIM;
    }
}

// ---------------- launcher ----------------
extern "C" void kernel_launch(void* const* d_in, const int* in_sizes, int n_in,
                              void* d_out, int out_size)
{
    const float* x          = (const float*)d_in[0];
    const float* in_proj_w  = (const float*)d_in[1];
    const float* conv_w     = (const float*)d_in[2];
    const float* conv_b     = (const float*)d_in[3];
    const float* A_log      = (const float*)d_in[4];
    const float* D_param    = (const float*)d_in[5];
    const float* x_proj_w   = (const float*)d_in[6];
    const float* dt_proj_w  = (const float*)d_in[7];
    const float* dt_proj_b  = (const float*)d_in[8];
    const float* out_proj_w = (const float*)d_in[9];
    float* out = (float*)d_out;

    float *xcin, *xdbl, *xpart, *sP, *sS, *sI;
    __half *gate, *xch, *deltah, *xh, *whin, *whout, *whdt, *whxp, *dtin, *ygh;
    cudaGetSymbolAddress((void**)&xcin,  g_xcin);
    cudaGetSymbolAddress((void**)&gate,  g_gate);
    cudaGetSymbolAddress((void**)&xch,   g_xch);
    cudaGetSymbolAddress((void**)&xdbl,  g_xdbl);
    cudaGetSymbolAddress((void**)&deltah,g_deltah);
    cudaGetSymbolAddress((void**)&xh,    g_xh);
    cudaGetSymbolAddress((void**)&whin,  g_wh_in);
    cudaGetSymbolAddress((void**)&whout, g_wh_out);
    cudaGetSymbolAddress((void**)&whdt,  g_wh_dt);
    cudaGetSymbolAddress((void**)&whxp,  g_wh_xp);
    cudaGetSymbolAddress((void**)&dtin,  g_dtin);
    cudaGetSymbolAddress((void**)&ygh,   g_ygh);
    cudaGetSymbolAddress((void**)&xpart, g_xpart);
    cudaGetSymbolAddress((void**)&sP,    g_scanP);
    cudaGetSymbolAddress((void**)&sS,    g_scanS);
    cudaGetSymbolAddress((void**)&sI,    g_scanI);

    const int M = MROWS;

    cudaFuncSetAttribute(gemm_h<0>, cudaFuncAttributeMaxDynamicSharedMemorySize, GEMM_SMEM);
    cudaFuncSetAttribute(gemm_h<1>, cudaFuncAttributeMaxDynamicSharedMemorySize, GEMM_SMEM);
    cudaFuncSetAttribute(gemm_h<2>, cudaFuncAttributeMaxDynamicSharedMemorySize, GEMM_SMEM);

    // 0. fp16-round all GEMM operands (single fused bandwidth pass)
    cvt_all_kernel<<<(CVT_TOTAL + 255)/256, 256>>>(
        x, xh, in_proj_w, whin, out_proj_w, whout, dt_proj_w, whdt,
        x_proj_w, whxp);

    // 1. in_proj (split epilogue): xcin fp32 + pre-gated silu(z) fp16
    gemm_h<2><<<dim3((2*DIM)/128, M/128), 256, GEMM_SMEM>>>(
        xh, DIM, whin, DIM, xcin, DIM, gate, nullptr, DIM);

    // 2. depthwise conv1d -> xch (fp16)
    conv_kernel<<<(M*DIM)/256, 256>>>(xcin, conv_w, conv_b, xch);

    // 3. x_proj split-K fp16 mma: partials then reduce (+fused dtin emit)
    xproj_mma<<<dim3(SK, M/128), 256>>>(xch, whxp, xpart);
    xproj_reduce<<<(M*XD + 255)/256, 256>>>(xpart, xdbl, dtin);

    // 4. dt_proj + softplus -> fp16 delta
    gemm_h<1><<<dim3(DIM/128, M/128), 256, GEMM_SMEM>>>(
        dtin, DTR, whdt, DTR, nullptr, DIM, deltah, dt_proj_b, DTR);

    // 5. chunked selective scan (parallelism x8 over time chunks)
    scan_part<<<dim3((BATCH*DIM)/16, NC), 256>>>(deltah, xch, xdbl, A_log, sP, sS);
    scan_chain<<<(BATCH*DIM*NST)/256, 256>>>(sP, sS, sI);
    scan_emit<<<dim3((BATCH*DIM)/16, NC), 256>>>(deltah, xch, xdbl, gate, A_log,
                                                 D_param, sI, ygh);

    // 6. out_proj: out = yg @ out_proj_w^T  (4096 x 1024 x 1024)
    gemm_h<0><<<dim3(DIM/128, M/128), 256, GEMM_SMEM>>>(
        ygh, DIM, whout, DIM, out, DIM, nullptr, nullptr, DIM);
}

// round 17
// speedup vs baseline: 1.1689x; 1.0736x over previous
#include <cuda_runtime.h>
#include <cuda_fp16.h>
#include <cstdint>

#define BATCH 2
#define SEQ   2048
#define DIM   1024
#define NST   16
#define DTR   64
#define XD    96   /* dt_rank + 2*N */

#define MROWS (BATCH*SEQ) /* 4096 */

#define NC 8      /* scan chunks */
#define LC 256    /* chunk length = SEQ/NC */

#define SK 8      /* x_proj split-K factor (KS = 128) */

#define LOG2E 1.4426950408889634f

// ---------------- scratch (allocation-free: __device__ globals) ----------------
__device__ float  g_xcin[(size_t)MROWS * DIM];    // 16.8 MB (in_proj xc-half, pre-conv)
__device__ __half g_gate[(size_t)MROWS * DIM];    // 8.4 MB  (silu(z), fp16)
__device__ __half g_xch[(size_t)MROWS * DIM];     // 8.4 MB  (conv out fp16: scan + x_proj)
__device__ float  g_xdbl[(size_t)MROWS * XD];     // 1.6 MB
__device__ __half g_deltah[(size_t)MROWS * DIM];  // 8.4 MB  (fp16 delta)
// fp16 GEMM operands
__device__ __half g_xh[(size_t)MROWS * DIM];      // 8.4 MB
__device__ __half g_wh_in[(size_t)2 * DIM * DIM]; // 4.2 MB
__device__ __half g_wh_out[(size_t)DIM * DIM];    // 2.1 MB
__device__ __half g_wh_dt[(size_t)DIM * DTR];     // 0.13 MB
__device__ __half g_wh_xp[(size_t)XD * DIM];      // 0.2 MB  (x_proj_w fp16)
__device__ __half g_dtin[(size_t)MROWS * DTR];    // 0.5 MB
__device__ __half g_ygh[(size_t)MROWS * DIM];     // 8.4 MB
// x_proj split-K partials
__device__ float g_xpart[(size_t)SK * MROWS * XD]; // 12.6 MB
// chunked-scan chain state: layout [(b*NC + c) * DIM*NST + d*NST + n]
__device__ float g_scanP[(size_t)BATCH * NC * DIM * NST];  // 1.0 MB
__device__ float g_scanS[(size_t)BATCH * NC * DIM * NST];  // 1.0 MB
__device__ float g_scanI[(size_t)BATCH * NC * DIM * NST];  // 1.0 MB

// ---------------- helpers ----------------
__device__ __forceinline__ float softplusf(float x) {
    return (x > 20.f) ? x : log1pf(__expf(x));
}

__device__ __forceinline__ float siluf(float z) {
    return z * __fdividef(1.f, 1.f + __expf(-z));
}

__device__ __forceinline__ uint32_t smem_u32(const void* p) {
    uint32_t a;
    asm("{ .reg .u64 t; cvta.to.shared.u64 t, %1; cvt.u32.u64 %0, t; }"
        : "=r"(a) : "l"(p));
    return a;
}

// ---------------- fused fp16 convert pass (one launch for all operands) --------
#define CVT_N_X    (MROWS*DIM/4)        /* 1048576 */
#define CVT_N_WIN  (2*DIM*DIM/4)        /*  524288 */
#define CVT_N_WOUT (DIM*DIM/4)          /*  262144 */
#define CVT_N_WDT  (DIM*DTR/4)          /*   16384 */
#define CVT_N_WXP  (XD*DIM/4)           /*   24576 */
#define CVT_TOTAL  (CVT_N_X + CVT_N_WIN + CVT_N_WOUT + CVT_N_WDT + CVT_N_WXP)

__global__ void cvt_all_kernel(const float* __restrict__ x,    __half* __restrict__ xh,
                               const float* __restrict__ win,  __half* __restrict__ whin,
                               const float* __restrict__ wout, __half* __restrict__ whout,
                               const float* __restrict__ wdt,  __half* __restrict__ whdt,
                               const float* __restrict__ wxp,  __half* __restrict__ whxp)
{
    int i = blockIdx.x * blockDim.x + threadIdx.x;
    const float* src; __half* dst;
    if (i < CVT_N_X)                        { src = x;    dst = xh; }
    else if ((i -= CVT_N_X)   < CVT_N_WIN)  { src = win;  dst = whin; }
    else if ((i -= CVT_N_WIN) < CVT_N_WOUT) { src = wout; dst = whout; }
    else if ((i -= CVT_N_WOUT) < CVT_N_WDT) { src = wdt;  dst = whdt; }
    else if ((i -= CVT_N_WDT) < CVT_N_WXP)  { src = wxp;  dst = whxp; }
    else return;
    float4 v = reinterpret_cast<const float4*>(src)[i];
    __half2 lo = __floats2half2_rn(v.x, v.y);
    __half2 hi = __floats2half2_rn(v.z, v.w);
    reinterpret_cast<__half2*>(dst)[2*i]   = lo;
    reinterpret_cast<__half2*>(dst)[2*i+1] = hi;
}

// =====================================================================
// cp.async-pipelined fp16 m16n8k16 GEMM: C = A(MxK) * B(NxK)^T.
// Operands in __half, K-contiguous. BM=128, BN=128, BK=64 halves
// (128B rows -> 8x16B chunks, XOR swizzle chunk^=row&7).
// 256 threads (8 warps), warp tile 64x32, 3-stage ring (32KB/stage),
// __launch_bounds__(256,2) -> 2 CTAs/SM (16 warps) for latency hiding.
// ACT: 0 = C fp32
//      1 = Ch fp16 = softplus(acc + bias[n])            (delta)
//      2 = n<DIM: C fp32 (xcin) ; n>=DIM: Ch fp16 = silu (gate)
// =====================================================================
#define GEMM_SMEM (3*32768)

template<int ACT>
__global__ void __launch_bounds__(256, 2)
gemm_h(const __half* __restrict__ A, int lda,
       const __half* __restrict__ Bm, int ldb,
       float* __restrict__ C, int ldc,
       __half* __restrict__ Ch,
       const float* __restrict__ bias, int K)
{
    extern __shared__ __align__(128) uint32_t sm[];
    const uint32_t sbase = smem_u32(sm);

    const int tid  = threadIdx.x;
    const int wid  = tid >> 5;
    const int lane = tid & 31;
    const int g    = lane >> 2;
    const int tig  = lane & 3;
    const int wm   = (wid >> 2) * 64;   // 2 warp rows over 128
    const int wn   = (wid & 3) * 32;    // 4 warp cols over 128
    const int m0   = blockIdx.y * 128;
    const int n0   = blockIdx.x * 128;

    const int rb    = tid >> 3;        // 0..31
    const int chk   = tid & 7;
    const uint32_t cxoff = (uint32_t)((chk ^ (rb & 7)) << 4);
    const __half* gA0 = A  + (size_t)(m0 + rb) * lda + chk * 8;
    const __half* gB0 = Bm + (size_t)(n0 + rb) * ldb + chk * 8;
    const uint32_t sOff = rb * 128 + cxoff;

    const int T = K >> 6;

    auto issue_tile = [&](int t) {
        const int stage = t % 3;
        const int k0 = t << 6;
        const uint32_t sA = sbase + stage * 32768 + sOff;
        const uint32_t sB = sA + 16384;
        const __half* gA = gA0 + k0;
        const __half* gB = gB0 + k0;
#pragma unroll
        for (int i = 0; i < 4; i++)   // A: 128 rows
            asm volatile("cp.async.cg.shared.global [%0], [%1], 16;"
                         :: "r"(sA + i * 4096), "l"(gA + (size_t)32 * i * lda));
#pragma unroll
        for (int i = 0; i < 4; i++)   // B: 128 rows
            asm volatile("cp.async.cg.shared.global [%0], [%1], 16;"
                         :: "r"(sB + i * 4096), "l"(gB + (size_t)32 * i * ldb));
        asm volatile("cp.async.commit_group;" ::: "memory");
    };

    float c[4][4][4];
#pragma unroll
    for (int i = 0; i < 4; i++)
#pragma unroll
        for (int j = 0; j < 4; j++)
#pragma unroll
            for (int r = 0; r < 4; r++) c[i][j][r] = 0.f;

    const int rrA = ((lane >> 3) & 1) * 8 + (lane & 7);
    const int khA = lane >> 4;
    const int rrB = lane & 7;
    const int khB = (lane >> 3) & 1;

    auto compute = [&](int stage) {
        const uint32_t Abase = sbase + stage * 32768;
        const uint32_t Bbase = Abase + 16384;
#pragma unroll
        for (int ks = 0; ks < 4; ks++) {
            const int c0 = 2 * ks;
            uint32_t a[4][4], b[4][2];
#pragma unroll
            for (int mt = 0; mt < 4; mt++) {
                const int row = wm + mt * 16 + rrA;
                const uint32_t addr = Abase + row * 128
                                    + (((c0 + khA) ^ (row & 7)) << 4);
                asm volatile(
                    "ldmatrix.sync.aligned.m8n8.x4.shared.b16 {%0,%1,%2,%3}, [%4];"
                    : "=r"(a[mt][0]), "=r"(a[mt][1]), "=r"(a[mt][2]), "=r"(a[mt][3])
                    : "r"(addr));
            }
#pragma unroll
            for (int nt = 0; nt < 4; nt++) {
                const int row = wn + nt * 8 + rrB;
                const uint32_t addr = Bbase + row * 128
                                    + (((c0 + khB) ^ (row & 7)) << 4);
                asm volatile(
                    "ldmatrix.sync.aligned.m8n8.x2.shared.b16 {%0,%1}, [%2];"
                    : "=r"(b[nt][0]), "=r"(b[nt][1])
                    : "r"(addr));
            }
#pragma unroll
            for (int mt = 0; mt < 4; mt++)
#pragma unroll
                for (int nt = 0; nt < 4; nt++) {
                    asm volatile(
                        "mma.sync.aligned.m16n8k16.row.col.f32.f16.f16.f32 "
                        "{%0,%1,%2,%3}, {%4,%5,%6,%7}, {%8,%9}, {%0,%1,%2,%3};\n"
                        : "+f"(c[mt][nt][0]), "+f"(c[mt][nt][1]),
                          "+f"(c[mt][nt][2]), "+f"(c[mt][nt][3])
                        : "r"(a[mt][0]), "r"(a[mt][1]), "r"(a[mt][2]), "r"(a[mt][3]),
                          "r"(b[nt][0]), "r"(b[nt][1]));
                }
        }
    };

    issue_tile(0);
    if (T > 1) issue_tile(1);

    for (int t = 0; t < T; ++t) {
        if (t + 2 < T) {
            issue_tile(t + 2);
            asm volatile("cp.async.wait_group 2;" ::: "memory");
        } else {
            asm volatile("cp.async.wait_group 0;" ::: "memory");
        }
        __syncthreads();
        compute(t % 3);
        __syncthreads();
    }

    // ---- epilogue ----
#pragma unroll
    for (int mt = 0; mt < 4; mt++) {
        int r = m0 + wm + mt * 16 + g;
#pragma unroll
        for (int nt = 0; nt < 4; nt++) {
            int n = n0 + wn + nt * 8 + tig * 2;
            float v0 = c[mt][nt][0], v1 = c[mt][nt][1];
            float v2 = c[mt][nt][2], v3 = c[mt][nt][3];
            if (ACT == 0) {
                *reinterpret_cast<float2*>(C + (size_t)r * ldc + n)       = make_float2(v0, v1);
                *reinterpret_cast<float2*>(C + (size_t)(r + 8) * ldc + n) = make_float2(v2, v3);
            } else if (ACT == 1) {
                float b0 = bias[n], b1 = bias[n + 1];
                *reinterpret_cast<__half2*>(Ch + (size_t)r * ldc + n) =
                    __floats2half2_rn(softplusf(v0 + b0), softplusf(v1 + b1));
                *reinterpret_cast<__half2*>(Ch + (size_t)(r + 8) * ldc + n) =
                    __floats2half2_rn(softplusf(v2 + b0), softplusf(v3 + b1));
            } else { // ACT == 2: split xz
                if (n < DIM) {
                    *reinterpret_cast<float2*>(C + (size_t)r * DIM + n)       = make_float2(v0, v1);
                    *reinterpret_cast<float2*>(C + (size_t)(r + 8) * DIM + n) = make_float2(v2, v3);
                } else {
                    int nz = n - DIM;
                    *reinterpret_cast<__half2*>(Ch + (size_t)r * DIM + nz) =
                        __floats2half2_rn(siluf(v0), siluf(v1));
                    *reinterpret_cast<__half2*>(Ch + (size_t)(r + 8) * DIM + nz) =
                        __floats2half2_rn(siluf(v2), siluf(v3));
                }
            }
        }
    }
}

// =====================================================================
// x_proj split-K fp16 MMA: part[sk] = xch(128 rows) @ W[96, K]^T over
// K-slice sk (KS = 128 halves -> two 64-k tiles looped in-CTA).
// 8 warps, warp tile 64x24, fp32 partials. grid = (SK, M/128).
// =====================================================================
__global__ void __launch_bounds__(256)
xproj_mma(const __half* __restrict__ A,      // xch [M, DIM]
          const __half* __restrict__ W,      // x_proj_w fp16 [XD, DIM]
          float* __restrict__ part)          // [SK, M, XD]
{
    constexpr int KS = DIM / SK;   // 128 halves per split
    __shared__ __align__(128) uint8_t smb[28672];   // A 16KB + B 12KB
    const uint32_t sbase = smem_u32(smb);

    const int tid  = threadIdx.x;
    const int wid  = tid >> 5;
    const int lane = tid & 31;
    const int g    = lane >> 2;
    const int tig  = lane & 3;
    const int wm   = (wid >> 2) * 64;   // 2 warp rows over 128
    const int wn   = (wid & 3) * 24;    // 4 warp cols over 96
    const int m0   = blockIdx.y * 128;
    const int kb   = blockIdx.x * KS;   // K-slice start (halves)

    const int rb  = tid >> 3;           // 0..31
    const int chk = tid & 7;
    const uint32_t cxoff = (uint32_t)((chk ^ (rb & 7)) << 4);
    const uint32_t sOff = rb * 128 + cxoff;

    float c[4][3][4];
#pragma unroll
    for (int i = 0; i < 4; i++)
#pragma unroll
        for (int j = 0; j < 3; j++)
#pragma unroll
            for (int r = 0; r < 4; r++) c[i][j][r] = 0.f;

    const int rrA = ((lane >> 3) & 1) * 8 + (lane & 7);
    const int khA = lane >> 4;
    const int rrB = lane & 7;
    const int khB = (lane >> 3) & 1;

#pragma unroll
    for (int tt = 0; tt < KS / 64; ++tt) {
        const int k0 = kb + tt * 64;
        const __half* gA = A + (size_t)(m0 + rb) * DIM + k0 + chk * 8;
        const __half* gB = W + (size_t)rb * DIM + k0 + chk * 8;
#pragma unroll
        for (int i = 0; i < 4; i++)
            asm volatile("cp.async.cg.shared.global [%0], [%1], 16;"
                         :: "r"(sbase + sOff + i * 4096), "l"(gA + (size_t)32 * i * DIM));
#pragma unroll
        for (int i = 0; i < 3; i++)
            asm volatile("cp.async.cg.shared.global [%0], [%1], 16;"
                         :: "r"(sbase + 16384 + sOff + i * 4096), "l"(gB + (size_t)32 * i * DIM));
        asm volatile("cp.async.commit_group;" ::: "memory");
        asm volatile("cp.async.wait_group 0;" ::: "memory");
        __syncthreads();

#pragma unroll
        for (int ks = 0; ks < 4; ks++) {
            const int c0 = 2 * ks;
            uint32_t a[4][4], b[3][2];
#pragma unroll
            for (int mt = 0; mt < 4; mt++) {
                const int row = wm + mt * 16 + rrA;
                const uint32_t addr = sbase + row * 128
                                    + (((c0 + khA) ^ (row & 7)) << 4);
                asm volatile(
                    "ldmatrix.sync.aligned.m8n8.x4.shared.b16 {%0,%1,%2,%3}, [%4];"
                    : "=r"(a[mt][0]), "=r"(a[mt][1]), "=r"(a[mt][2]), "=r"(a[mt][3])
                    : "r"(addr));
            }
#pragma unroll
            for (int nt = 0; nt < 3; nt++) {
                const int row = wn + nt * 8 + rrB;
                const uint32_t addr = sbase + 16384 + row * 128
                                    + (((c0 + khB) ^ (row & 7)) << 4);
                asm volatile(
                    "ldmatrix.sync.aligned.m8n8.x2.shared.b16 {%0,%1}, [%2];"
                    : "=r"(b[nt][0]), "=r"(b[nt][1])
                    : "r"(addr));
            }
#pragma unroll
            for (int mt = 0; mt < 4; mt++)
#pragma unroll
                for (int nt = 0; nt < 3; nt++) {
                    asm volatile(
                        "mma.sync.aligned.m16n8k16.row.col.f32.f16.f16.f32 "
                        "{%0,%1,%2,%3}, {%4,%5,%6,%7}, {%8,%9}, {%0,%1,%2,%3};\n"
                        : "+f"(c[mt][nt][0]), "+f"(c[mt][nt][1]),
                          "+f"(c[mt][nt][2]), "+f"(c[mt][nt][3])
                        : "r"(a[mt][0]), "r"(a[mt][1]), "r"(a[mt][2]), "r"(a[mt][3]),
                          "r"(b[nt][0]), "r"(b[nt][1]));
                }
        }
        __syncthreads();
    }

    float* dst = part + (size_t)blockIdx.x * MROWS * XD;
#pragma unroll
    for (int mt = 0; mt < 4; mt++) {
        int r = m0 + wm + mt * 16 + g;
#pragma unroll
        for (int nt = 0; nt < 3; nt++) {
            int n = wn + nt * 8 + tig * 2;
            *reinterpret_cast<float2*>(dst + (size_t)r * XD + n) =
                make_float2(c[mt][nt][0], c[mt][nt][1]);
            *reinterpret_cast<float2*>(dst + (size_t)(r + 8) * XD + n) =
                make_float2(c[mt][nt][2], c[mt][nt][3]);
        }
    }
}

// reduce SK partials -> xdbl; fused dtin (fp16-rounded first 64 cols)
__global__ void __launch_bounds__(256)
xproj_reduce(const float* __restrict__ part,
             float* __restrict__ xdbl,
             __half* __restrict__ dtin)
{
    int i = blockIdx.x * blockDim.x + threadIdx.x;   // over MROWS*XD
    if (i >= MROWS * XD) return;
    float s = 0.f;
#pragma unroll
    for (int sk = 0; sk < SK; sk++)
        s += part[(size_t)sk * MROWS * XD + i];
    xdbl[i] = s;
    int n = i % XD;
    if (n < DTR) {
        int m = i / XD;
        dtin[(size_t)m * DTR + n] = __float2half_rn(s);
    }
}

// ---------------- depthwise conv1d k=3 pad=1 (dense xcin input) ----------------
// Emits fp16 xch (scan + x_proj).
__global__ void conv_kernel(const float* __restrict__ xcin,
                            const float* __restrict__ w,
                            const float* __restrict__ bconv,
                            __half* __restrict__ xch)
{
    int idx = blockIdx.x * blockDim.x + threadIdx.x;   // over MROWS*DIM
    if (idx >= MROWS * DIM) return;
    int d = idx & (DIM - 1);
    int l = (idx >> 10) & (SEQ - 1);
    const float* base = xcin + idx;
    float w0 = w[d*3+0], w1 = w[d*3+1], w2 = w[d*3+2];
    float acc = bconv[d];
    if (l > 0)       acc = fmaf(w0, base[-DIM], acc);
    acc = fmaf(w1, base[0], acc);
    if (l < SEQ - 1) acc = fmaf(w2, base[DIM], acc);
    xch[idx] = __float2half_rn(acc);
}

// =====================================================================
// Chunked selective scan (3 passes; recurrence is linear -> exact).
// Warp = 2 channels x 16 states. Lanes 0-15: chan0; 16-31: chan1.
// delta/u read fp16; B/C read fp32 from xdbl; gate read fp16.
// dA computed as exp2f(dt * (A*log2e)) — FMUL+EX2, one op fewer than expf.
// =====================================================================

// Pass A: per-chunk P = prod dA and zero-init partial state S
__global__ void __launch_bounds__(256)
scan_part(const __half* __restrict__ delta,
          const __half* __restrict__ u,
          const float* __restrict__ xdbl,
          const float* __restrict__ A_log,
          float* __restrict__ Pout,
          float* __restrict__ Sout)
{
    const int lane = threadIdx.x & 31;
    const int warp = threadIdx.x >> 5;
    const int n = lane & 15;
    const int chan = blockIdx.x * 16 + (warp << 1) + (lane >> 4);
    const int b = chan >> 10;
    const int d = chan & (DIM - 1);
    const int c = blockIdx.y;

    const float Ae = -__expf(__ldg(A_log + d*NST + n)) * LOG2E;

    const size_t row0 = (size_t)b * SEQ + (size_t)c * LC;
    const __half* pD = delta + row0 * DIM + d;
    const __half* pU = u     + row0 * DIM + d;
    const float* pBC = xdbl  + row0 * XD + DTR + n;

    float s = 0.f, P = 1.f;
#pragma unroll 8
    for (int t = 0; t < LC; ++t) {
        float dt = __half2float(__ldg(pD));
        float uu = __half2float(__ldg(pU));
        float Bn = __ldg(pBC);
        float dA = exp2f(dt * Ae);
        s = fmaf(dA, s, dt * Bn * uu);
        P *= dA;
        pD += DIM; pU += DIM; pBC += XD;
    }
    const size_t o = (((size_t)b * NC + c) * DIM + d) * NST + n;
    Pout[o] = P;
    Sout[o] = s;
}

// Pass B: sequential chain over chunks -> exact initial state per chunk
__global__ void __launch_bounds__(256)
scan_chain(const float* __restrict__ P,
           const float* __restrict__ S,
           float* __restrict__ I)
{
    const int tid = blockIdx.x * blockDim.x + threadIdx.x;  // 0..32767
    const int b = tid >> 14;            // / (DIM*NST)
    const int rest = tid & 16383;       // d*NST + n
    float s = 0.f;
#pragma unroll
    for (int c = 0; c < NC; ++c) {
        const size_t o = (((size_t)b * NC + c) << 14) + rest;
        I[o] = s;
        s = fmaf(P[o], s, S[o]);
    }
}

// Pass C: re-run each chunk from its initial state, emit gated y (fp16)
__global__ void __launch_bounds__(256)
scan_emit(const __half* __restrict__ delta,
          const __half* __restrict__ u,
          const float* __restrict__ xdbl,
          const __half* __restrict__ gate,
          const float* __restrict__ A_log,
          const float* __restrict__ Dp,
          const float* __restrict__ I,
          __half* __restrict__ yg)
{
    const int lane = threadIdx.x & 31;
    const int warp = threadIdx.x >> 5;
    const int n = lane & 15;
    const int chan = blockIdx.x * 16 + (warp << 1) + (lane >> 4);
    const int b = chan >> 10;
    const int d = chan & (DIM - 1);
    const int c = blockIdx.y;

    const float Ae   = -__expf(__ldg(A_log + d*NST + n)) * LOG2E;
    const float Dpar = __ldg(Dp + d);

    const size_t row0 = (size_t)b * SEQ + (size_t)c * LC;
    const __half* pD = delta + row0 * DIM + d;
    const __half* pU = u     + row0 * DIM + d;
    const float* pBC = xdbl  + row0 * XD;
    const __half* pG = gate  + row0 * DIM + d;
    __half*      pY  = yg    + row0 * DIM + d;

    float s = I[(((size_t)b * NC + c) * DIM + d) * NST + n];

#pragma unroll 8
    for (int t = 0; t < LC; ++t) {
        float dt = __half2float(__ldg(pD));
        float uu = __half2float(__ldg(pU));
        float Bn = __ldg(pBC + DTR + n);
        float Cn = __ldg(pBC + DTR + NST + n);

        float dA = exp2f(dt * Ae);
        s = fmaf(dA, s, dt * Bn * uu);

        float p = s * Cn;
        p += __shfl_xor_sync(0xffffffffu, p, 1);
        p += __shfl_xor_sync(0xffffffffu, p, 2);
        p += __shfl_xor_sync(0xffffffffu, p, 4);
        p += __shfl_xor_sync(0xffffffffu, p, 8);

        if (n == 0) {
            float gt = __half2float(__ldg(pG));
            float val = fmaf(uu, Dpar, p) * gt;
            pY[0] = __float2half_rn(val);
        }
        pD += DIM; pU += DIM; pBC += XD; pG += DIM; pY += DIM;
    }
}

// ---------------- launcher ----------------
extern "C" void kernel_launch(void* const* d_in, const int* in_sizes, int n_in,
                              void* d_out, int out_size)
{
    const float* x          = (const float*)d_in[0];
    const float* in_proj_w  = (const float*)d_in[1];
    const float* conv_w     = (const float*)d_in[2];
    const float* conv_b     = (const float*)d_in[3];
    const float* A_log      = (const float*)d_in[4];
    const float* D_param    = (const float*)d_in[5];
    const float* x_proj_w   = (const float*)d_in[6];
    const float* dt_proj_w  = (const float*)d_in[7];
    const float* dt_proj_b  = (const float*)d_in[8];
    const float* out_proj_w = (const float*)d_in[9];
    float* out = (float*)d_out;

    float *xcin, *xdbl, *xpart, *sP, *sS, *sI;
    __half *gate, *xch, *deltah, *xh, *whin, *whout, *whdt, *whxp, *dtin, *ygh;
    cudaGetSymbolAddress((void**)&xcin,  g_xcin);
    cudaGetSymbolAddress((void**)&gate,  g_gate);
    cudaGetSymbolAddress((void**)&xch,   g_xch);
    cudaGetSymbolAddress((void**)&xdbl,  g_xdbl);
    cudaGetSymbolAddress((void**)&deltah,g_deltah);
    cudaGetSymbolAddress((void**)&xh,    g_xh);
    cudaGetSymbolAddress((void**)&whin,  g_wh_in);
    cudaGetSymbolAddress((void**)&whout, g_wh_out);
    cudaGetSymbolAddress((void**)&whdt,  g_wh_dt);
    cudaGetSymbolAddress((void**)&whxp,  g_wh_xp);
    cudaGetSymbolAddress((void**)&dtin,  g_dtin);
    cudaGetSymbolAddress((void**)&ygh,   g_ygh);
    cudaGetSymbolAddress((void**)&xpart, g_xpart);
    cudaGetSymbolAddress((void**)&sP,    g_scanP);
    cudaGetSymbolAddress((void**)&sS,    g_scanS);
    cudaGetSymbolAddress((void**)&sI,    g_scanI);

    const int M = MROWS;

    cudaFuncSetAttribute(gemm_h<0>, cudaFuncAttributeMaxDynamicSharedMemorySize, GEMM_SMEM);
    cudaFuncSetAttribute(gemm_h<1>, cudaFuncAttributeMaxDynamicSharedMemorySize, GEMM_SMEM);
    cudaFuncSetAttribute(gemm_h<2>, cudaFuncAttributeMaxDynamicSharedMemorySize, GEMM_SMEM);

    // 0. fp16-round all GEMM operands (single fused bandwidth pass)
    cvt_all_kernel<<<(CVT_TOTAL + 255)/256, 256>>>(
        x, xh, in_proj_w, whin, out_proj_w, whout, dt_proj_w, whdt,
        x_proj_w, whxp);

    // 1. in_proj (split epilogue): xcin fp32 + pre-gated silu(z) fp16
    gemm_h<2><<<dim3((2*DIM)/128, M/128), 256, GEMM_SMEM>>>(
        xh, DIM, whin, DIM, xcin, DIM, gate, nullptr, DIM);

    // 2. depthwise conv1d -> xch (fp16)
    conv_kernel<<<(M*DIM)/256, 256>>>(xcin, conv_w, conv_b, xch);

    // 3. x_proj split-K fp16 mma: partials then reduce (+fused dtin emit)
    xproj_mma<<<dim3(SK, M/128), 256>>>(xch, whxp, xpart);
    xproj_reduce<<<(M*XD + 255)/256, 256>>>(xpart, xdbl, dtin);

    // 4. dt_proj + softplus -> fp16 delta
    gemm_h<1><<<dim3(DIM/128, M/128), 256, GEMM_SMEM>>>(
        dtin, DTR, whdt, DTR, nullptr, DIM, deltah, dt_proj_b, DTR);

    // 5. chunked selective scan (parallelism x8 over time chunks)
    scan_part<<<dim3((BATCH*DIM)/16, NC), 256>>>(deltah, xch, xdbl, A_log, sP, sS);
    scan_chain<<<(BATCH*DIM*NST)/256, 256>>>(sP, sS, sI);
    scan_emit<<<dim3((BATCH*DIM)/16, NC), 256>>>(deltah, xch, xdbl, gate, A_log,
                                                 D_param, sI, ygh);

    // 6. out_proj: out = yg @ out_proj_w^T  (4096 x 1024 x 1024)
    gemm_h<0><<<dim3(DIM/128, M/128), 256, GEMM_SMEM>>>(
        ygh, DIM, whout, DIM, out, DIM, nullptr, nullptr, DIM);
}